// round 1
// baseline (speedup 1.0000x reference)
#include <cuda_runtime.h>

// RandomShiftsAug: the reference's bilinear grid_sample degenerates to an
// exact integer shifted gather on the replicate-padded image:
//   out[n,c,j,i] = x[n,c, clamp(j+sy-4, 0, 83), clamp(i+sx-4, 0, 83)]
// Pure HBM-bound copy: 130 MB in + 130 MB out.

#define N_  512
#define C_  9
#define H_  84
#define W_  84
#define PAD_ 4

// Each thread produces one float4 of output (W=84 = 21 float4 chunks per row,
// chunks never straddle a row boundary).
__global__ __launch_bounds__(128) void random_shift_kernel(
    const float* __restrict__ x,
    const int*   __restrict__ shift,
    float*       __restrict__ out)
{
    const int total4 = N_ * C_ * H_ * (W_ / 4);   // 8,128,512
    int t = blockIdx.x * blockDim.x + threadIdx.x;
    if (t >= total4) return;

    int q   = t % (W_ / 4);        // float4 chunk within row
    int row = t / (W_ / 4);        // (n*C + c)*H + j
    int j   = row % H_;
    int nc  = row / H_;
    int n   = nc / C_;

    // shift[n,0,0,0] = sx (width), shift[n,0,0,1] = sy (height); values in [0, 2*pad]
    int sx = __ldg(&shift[2 * n + 0]);
    int sy = __ldg(&shift[2 * n + 1]);

    int srcy = j + sy - PAD_;
    srcy = min(max(srcy, 0), H_ - 1);

    const float* __restrict__ src = x + ((long)nc * H_ + srcy) * W_;

    int a = q * 4 + sx - PAD_;     // source column of first element; in [-4, 87]
    float4 v;
    v.x = __ldg(&src[min(max(a + 0, 0), W_ - 1)]);
    v.y = __ldg(&src[min(max(a + 1, 0), W_ - 1)]);
    v.z = __ldg(&src[min(max(a + 2, 0), W_ - 1)]);
    v.w = __ldg(&src[min(max(a + 3, 0), W_ - 1)]);

    reinterpret_cast<float4*>(out)[t] = v;
}

extern "C" void kernel_launch(void* const* d_in, const int* in_sizes, int n_in,
                              void* d_out, int out_size)
{
    const float* x     = (const float*)d_in[0];
    const int*   shift = (const int*)  d_in[1];
    // d_in[2] is pad (=4), fixed for this problem shape.
    float* out = (float*)d_out;

    const int total4 = N_ * C_ * H_ * (W_ / 4);
    const int threads = 128;
    const int blocks  = (total4 + threads - 1) / threads;
    random_shift_kernel<<<blocks, threads>>>(x, shift, out);
}